// round 13
// baseline (speedup 1.0000x reference)
#include <cuda_runtime.h>
#include <cstdint>

#define NN 50000
#define EE 800000
#define DIM 128

// Scratch (static device globals — no allocation at launch time).
__device__ float g_buf[3u * NN * DIM];        // per-type src-sum accumulators, 76.8 MB
__device__ float cnt_buf[3u * NN];            // per-type in-degree counts (float, exact)
__device__ float wcat_buf[4 * DIM * DIM];     // concatenated weights, [k][o] layout, k=0..511

// ---------------------------------------------------------------------------
// Phase 0: zero accumulators
// ---------------------------------------------------------------------------
__global__ void zero_kernel() {
    const float4 z = make_float4(0.f, 0.f, 0.f, 0.f);
    size_t i = (size_t)blockIdx.x * blockDim.x + threadIdx.x;
    const size_t ng = (size_t)3 * NN * DIM / 4;   // 4.8M float4
    if (i < ng) reinterpret_cast<float4*>(g_buf)[i] = z;
    if (i < (size_t)(3 * NN) / 4) reinterpret_cast<float4*>(cnt_buf)[i] = z;
}

// ---------------------------------------------------------------------------
// Phase 0b: build Wcat[k][o] = W_{k/128}[o][k%128]  (k-major, o contiguous)
// ---------------------------------------------------------------------------
__global__ void wprep_kernel(const float* __restrict__ W0, const float* __restrict__ W1,
                             const float* __restrict__ W2, const float* __restrict__ Wh) {
    int idx = blockIdx.x * blockDim.x + threadIdx.x;   // < 512*128
    int k = idx >> 7;          // 0..511
    int o = idx & 127;
    int t = k >> 7;            // segment 0..3
    int kk = k & 127;
    const float* W = (t == 0) ? W0 : (t == 1) ? W1 : (t == 2) ? W2 : Wh;
    wcat_buf[idx] = W[o * DIM + kk];
}

// ---------------------------------------------------------------------------
// Phase 1: edge scatter. One warp per edge.
//   G_t[dst] += x[src];  cnt_t[dst] += 1     (−cnt·x[dst] fused into GEMM)
// ---------------------------------------------------------------------------
__global__ __launch_bounds__(256) void scatter_kernel(
    const float4* __restrict__ x4,
    const int* __restrict__ src, const int* __restrict__ dst,
    const int* __restrict__ et) {
    int warp = (int)(((size_t)blockIdx.x * blockDim.x + threadIdx.x) >> 5);
    int lane = threadIdx.x & 31;
    if (warp >= EE) return;
    int s = __ldg(src + warp);
    int d = __ldg(dst + warp);
    int t = __ldg(et + warp);

    float4 a = x4[(size_t)s * 32 + lane];

    float* p = g_buf + ((size_t)t * NN + d) * DIM + lane * 4;
    asm volatile("red.global.add.v4.f32 [%0], {%1, %2, %3, %4};"
                 :: "l"(p), "f"(a.x), "f"(a.y), "f"(a.z), "f"(a.w) : "memory");

    if (lane == 0) atomicAdd(cnt_buf + (size_t)t * NN + d, 1.0f);
}

// ---------------------------------------------------------------------------
// f32x2 packed FMA helpers (sm_100+; bit-identical to two scalar fp32 FMAs).
// b64 ("l") operands — ptxas rejects .f64-typed ("d") on fma.rn.f32x2.
// ---------------------------------------------------------------------------
using u64 = unsigned long long;

__device__ __forceinline__ void ffma2(u64& acc, u64 a, u64 b) {
    asm("fma.rn.f32x2 %0, %1, %2, %0;" : "+l"(acc) : "l"(a), "l"(b));
}
__device__ __forceinline__ u64 dup_f32(float v) {
    u64 r;
    asm("mov.b64 %0, {%1, %1};" : "=l"(r) : "f"(v));
    return r;
}
__device__ __forceinline__ void unpack2(u64 d, float& lo, float& hi) {
    asm("mov.b64 {%0, %1}, %2;" : "=f"(lo), "=f"(hi) : "l"(d));
}

// ---------------------------------------------------------------------------
// Phase 2: out[N,128] = A[N,512] @ Wcat[512,128] + bias(counts)
//   A[v, k] = G_t[v][kk] - cnt_t[v]*x[v][kk]   for t = k/128 < 3
//           = x[v][k-384]                      for k >= 384
// BM=64 x BN=128, BK=16, 256 threads, 4m x 8n microtile with f32x2 pairs
// PACKED ALONG N: B pairs read directly from smem (no dup), A scalars
// duplicated (4 movs/k). 1.5 LDS-bytes/MAC (R9 ratio) at 32 acc regs
// (R12 pressure) -> 4 CTAs/SM.
// ---------------------------------------------------------------------------
__global__ __launch_bounds__(256, 4) void gemm_kernel(
    const float* __restrict__ x,
    const float* __restrict__ b0, const float* __restrict__ b1,
    const float* __restrict__ b2, const float* __restrict__ bh,
    float* __restrict__ out) {
    __shared__ float As[2][16][68];     // [buf][k][m], padded 64+4
    __shared__ float Bs[2][16][128];    // [buf][k][n]
    __shared__ float cs[3][64];
    __shared__ float bias_s[4][128];

    const int tid = threadIdx.x;
    const int node0 = blockIdx.x * 64;

    if (tid < 64) {
        int v = node0 + tid;
        int vc = v < NN ? v : (NN - 1);
        bool ok = v < NN;
        cs[0][tid] = ok ? cnt_buf[0 * NN + vc] : 0.f;
        cs[1][tid] = ok ? cnt_buf[1 * NN + vc] : 0.f;
        cs[2][tid] = ok ? cnt_buf[2 * NN + vc] : 0.f;
    }
    {   // bias: 4 segments x 128 cols = 512 over 256 threads x2
#pragma unroll
        for (int r = 0; r < 2; r++) {
            int f = tid + r * 256;
            int t = f >> 7;
            int o = f & 127;
            const float* bp = (t == 0) ? b0 : (t == 1) ? b1 : (t == 2) ? b2 : bh;
            bias_s[t][o] = bp[o];
        }
    }
    __syncthreads();   // cs needed by fetchA below

    const int m0 = (tid >> 4) << 2;      // 0..60
    const int n0 = (tid & 15) << 3;      // 0..120 (float index, 8 per thread)

    // staging registers
    float4 ra, rb[2];

    // A-load: 64 rows x 16 k = 256 float4 over 256 threads
    // B-load: 16 k x 128 n = 512 float4 over 256 threads x2
    auto fetchA = [&](int kt) {
        const int seg = kt >> 3;                 // 0..3, uniform per kt
        int row = tid >> 2;                      // 0..63
        int q = tid & 3;
        int v = node0 + row;
        int vc = v < NN ? v : (NN - 1);          // clamp: branch-free
        int kk = ((kt & 7) << 4) + (q << 2);     // 0..124
        const float4* xp = reinterpret_cast<const float4*>(
            x + (size_t)vc * DIM + kk);
        if (seg < 3) {
            const float4* gp = reinterpret_cast<const float4*>(
                g_buf + ((size_t)seg * NN + vc) * DIM + kk);
            float4 g = __ldg(gp);
            float4 xv = __ldg(xp);
            float c = cs[seg][row];
            ra.x = fmaf(-c, xv.x, g.x);
            ra.y = fmaf(-c, xv.y, g.y);
            ra.z = fmaf(-c, xv.z, g.z);
            ra.w = fmaf(-c, xv.w, g.w);
        } else {
            ra = __ldg(xp);
        }
    };
    auto fetchB = [&](int kt) {
#pragma unroll
        for (int r = 0; r < 2; r++) {
            int f = tid + r * 256;
            int k = f >> 5;                      // 0..15
            int o = (f & 31) << 2;               // 0..124
            rb[r] = *reinterpret_cast<const float4*>(
                wcat_buf + (size_t)(kt * 16 + k) * DIM + o);
        }
    };
    auto storeA = [&](int buf) {
        int row = tid >> 2;
        int q = tid & 3;
        As[buf][q * 4 + 0][row] = ra.x;
        As[buf][q * 4 + 1][row] = ra.y;
        As[buf][q * 4 + 2][row] = ra.z;
        As[buf][q * 4 + 3][row] = ra.w;
    };
    auto storeB = [&](int buf) {
#pragma unroll
        for (int r = 0; r < 2; r++) {
            int f = tid + r * 256;
            int k = f >> 5;
            int o = (f & 31) << 2;
            *reinterpret_cast<float4*>(&Bs[buf][k][o]) = rb[r];
        }
    };

    // acc2[mi][jp]: row m0+mi, packed n-pair (n0+2*jp, n0+2*jp+1)
    u64 acc2[4][4];
#pragma unroll
    for (int i = 0; i < 4; i++)
#pragma unroll
        for (int j = 0; j < 4; j++) acc2[i][j] = 0ull;

    fetchA(0); fetchB(0);
    storeA(0); storeB(0);
    __syncthreads();

    for (int kt = 0; kt < 32; kt++) {
        int cur = kt & 1;
        int nxt = cur ^ 1;
        if (kt < 31) { fetchA(kt + 1); fetchB(kt + 1); }  // LDGs in flight

#pragma unroll
        for (int k = 0; k < 16; k++) {
            float4 a4 = *reinterpret_cast<const float4*>(&As[cur][k][m0]);
            ulonglong2 B0 = *reinterpret_cast<const ulonglong2*>(&Bs[cur][k][n0]);
            ulonglong2 B1 = *reinterpret_cast<const ulonglong2*>(&Bs[cur][k][n0 + 4]);
            u64 bd[4] = {B0.x, B0.y, B1.x, B1.y};
            u64 ad[4];
            ad[0] = dup_f32(a4.x);
            ad[1] = dup_f32(a4.y);
            ad[2] = dup_f32(a4.z);
            ad[3] = dup_f32(a4.w);
#pragma unroll
            for (int mi = 0; mi < 4; mi++)
#pragma unroll
                for (int jp = 0; jp < 4; jp++)
                    ffma2(acc2[mi][jp], ad[mi], bd[jp]);
        }

        if (kt < 31) { storeA(nxt); storeB(nxt); }
        __syncthreads();
    }

    // ---- epilogue: unpack (pairs are adjacent n), biases, store ----
#pragma unroll
    for (int mi = 0; mi < 4; mi++) {
        int row = m0 + mi;
        int v = node0 + row;
        if (v < NN) {
            float c0 = cs[0][row];
            float c1 = cs[1][row];
            float c2 = cs[2][row];
            float res[8];
#pragma unroll
            for (int jp = 0; jp < 4; jp++)
                unpack2(acc2[mi][jp], res[2 * jp], res[2 * jp + 1]);
#pragma unroll
            for (int j = 0; j < 8; j++) {
                int o = n0 + j;
                res[j] += c0 * bias_s[0][o]
                        + c1 * bias_s[1][o]
                        + c2 * bias_s[2][o]
                        + bias_s[3][o];
            }
            float* op = out + (size_t)v * DIM + n0;
            *reinterpret_cast<float4*>(op)     = make_float4(res[0], res[1], res[2], res[3]);
            *reinterpret_cast<float4*>(op + 4) = make_float4(res[4], res[5], res[6], res[7]);
        }
    }
}

// ---------------------------------------------------------------------------
// Launch
// ---------------------------------------------------------------------------
extern "C" void kernel_launch(void* const* d_in, const int* in_sizes, int n_in,
                              void* d_out, int out_size) {
    const float* n_feats = (const float*)d_in[0];
    const int*   src     = (const int*)d_in[1];
    const int*   dst     = (const int*)d_in[2];
    const int*   e_feats = (const int*)d_in[3];
    const float* W0 = (const float*)d_in[4];
    const float* b0 = (const float*)d_in[5];
    const float* W1 = (const float*)d_in[6];
    const float* b1 = (const float*)d_in[7];
    const float* W2 = (const float*)d_in[8];
    const float* b2 = (const float*)d_in[9];
    const float* Wh = (const float*)d_in[10];
    const float* bh = (const float*)d_in[11];
    float* out = (float*)d_out;

    // Phase 0: zero scratch
    {
        int total = 3 * NN * DIM / 4;
        int grid = (total + 255) / 256;
        zero_kernel<<<grid, 256>>>();
    }
    // Phase 0b: weight concat
    wprep_kernel<<<(4 * DIM * DIM) / 256, 256>>>(W0, W1, W2, Wh);

    // Phase 1: edge scatter — one warp per edge (src-only reads)
    {
        int grid = EE / 8;   // 8 warps (edges) per 256-thread block
        scatter_kernel<<<grid, 256>>>((const float4*)n_feats, src, dst, e_feats);
    }

    // Phase 2: fused GEMM (f32x2 packed along n, 4 CTAs/SM) + biases
    {
        int grid = (NN + 63) / 64;   // 782
        gemm_kernel<<<grid, 256>>>(n_feats, b0, b1, b2, bh, out);
    }
}

// round 15
// speedup vs baseline: 1.3931x; 1.3931x over previous
#include <cuda_runtime.h>
#include <cstdint>

#define NN 50000
#define EE 800000
#define DIM 128

// Scratch (static device globals — no allocation at launch time).
__device__ float g_buf[3u * NN * DIM];        // per-type src-sum accumulators, 76.8 MB
__device__ float cnt_buf[3u * NN];            // per-type in-degree counts (float, exact)

// ---------------------------------------------------------------------------
// Phase 0: zero accumulators
// ---------------------------------------------------------------------------
__global__ void zero_kernel() {
    const float4 z = make_float4(0.f, 0.f, 0.f, 0.f);
    size_t i = (size_t)blockIdx.x * blockDim.x + threadIdx.x;
    const size_t ng = (size_t)3 * NN * DIM / 4;   // 4.8M float4
    if (i < ng) reinterpret_cast<float4*>(g_buf)[i] = z;
    if (i < (size_t)(3 * NN) / 4) reinterpret_cast<float4*>(cnt_buf)[i] = z;
}

// ---------------------------------------------------------------------------
// Phase 1: edge scatter. One warp per edge.
//   G_t[dst] += x[src];  cnt_t[dst] += 1     (−cnt·x[dst] fused into GEMM)
// ---------------------------------------------------------------------------
__global__ __launch_bounds__(256) void scatter_kernel(
    const float4* __restrict__ x4,
    const int* __restrict__ src, const int* __restrict__ dst,
    const int* __restrict__ et) {
    int warp = (int)(((size_t)blockIdx.x * blockDim.x + threadIdx.x) >> 5);
    int lane = threadIdx.x & 31;
    if (warp >= EE) return;
    int s = __ldg(src + warp);
    int d = __ldg(dst + warp);
    int t = __ldg(et + warp);

    float4 a = x4[(size_t)s * 32 + lane];

    float* p = g_buf + ((size_t)t * NN + d) * DIM + lane * 4;
    asm volatile("red.global.add.v4.f32 [%0], {%1, %2, %3, %4};"
                 :: "l"(p), "f"(a.x), "f"(a.y), "f"(a.z), "f"(a.w) : "memory");

    if (lane == 0) atomicAdd(cnt_buf + (size_t)t * NN + d, 1.0f);
}

// ---------------------------------------------------------------------------
// 3xTF32 helpers (sm_80+ baseline features — legal on plain sm_100 target)
// ---------------------------------------------------------------------------
__device__ __forceinline__ void split_tf32(float a, uint32_t& hi, uint32_t& lo) {
    asm("cvt.rna.tf32.f32 %0, %1;" : "=r"(hi) : "f"(a));
    float l = a - __uint_as_float(hi);   // exact (Dekker)
    asm("cvt.rna.tf32.f32 %0, %1;" : "=r"(lo) : "f"(l));
}

__device__ __forceinline__ void mma_tf32(float* acc,
    uint32_t a0, uint32_t a1, uint32_t a2, uint32_t a3,
    uint32_t b0, uint32_t b1) {
    asm volatile(
        "mma.sync.aligned.m16n8k8.row.col.f32.tf32.tf32.f32 "
        "{%0,%1,%2,%3}, {%4,%5,%6,%7}, {%8,%9}, {%0,%1,%2,%3};"
        : "+f"(acc[0]), "+f"(acc[1]), "+f"(acc[2]), "+f"(acc[3])
        : "r"(a0), "r"(a1), "r"(a2), "r"(a3), "r"(b0), "r"(b1));
}

// ---------------------------------------------------------------------------
// Phase 2: out[N,128] = A[N,512] @ Wcat^T + bias(counts)  via 3xTF32 HMMA.
//   A[v,k] = G_t[v][kk] - cnt_t[v]*x[v][kk]  (t=k/128<3),  x[v][k-384] else.
// CTA: 128 nodes x 128 outs, 256 threads = 8 warps (2m x 4n), warp 64x32.
// K in 32 chunks of BK=16, single-buffer smem (hi/lo planes, 36KB static).
// Rotation layout rot(r,k) = (k + 4*((r>>1)&3)) & 15  -> all fragment
// LDS and the STS are 32-bank conflict-free.
// ---------------------------------------------------------------------------
__global__ __launch_bounds__(256, 2) void gemm_kernel(
    const float* __restrict__ x,
    const float* __restrict__ W0, const float* __restrict__ W1,
    const float* __restrict__ W2, const float* __restrict__ Wh,
    const float* __restrict__ b0, const float* __restrict__ b1,
    const float* __restrict__ b2, const float* __restrict__ bh,
    float* __restrict__ out) {
    __shared__ uint32_t Ah[128][16], Al[128][16];
    __shared__ uint32_t Bh[128][16], Bl[128][16];
    __shared__ float cs[3][128];
    __shared__ float bias_s[4][128];

    const int tid = threadIdx.x;
    const int lane = tid & 31;
    const int warp = tid >> 5;
    const int node0 = blockIdx.x * 128;

    if (tid < 128) {
        int v = node0 + tid;
        int vc = v < NN ? v : (NN - 1);
        bool ok = v < NN;
        cs[0][tid] = ok ? cnt_buf[0 * NN + vc] : 0.f;
        cs[1][tid] = ok ? cnt_buf[1 * NN + vc] : 0.f;
        cs[2][tid] = ok ? cnt_buf[2 * NN + vc] : 0.f;
    }
#pragma unroll
    for (int r = 0; r < 2; r++) {
        int f = tid + r * 256;
        int t = f >> 7, o = f & 127;
        const float* bp = (t == 0) ? b0 : (t == 1) ? b1 : (t == 2) ? b2 : bh;
        bias_s[t][o] = bp[o];
    }
    __syncthreads();

    const int wm = (warp >> 2) * 64;     // 0 / 64
    const int wn = (warp & 3) * 32;      // 0/32/64/96
    const int g = lane >> 2;             // 0..7
    const int c = lane & 3;              // 0..3

    float acc[4][4][4];                   // [mt][nt][c-frag]
#pragma unroll
    for (int i = 0; i < 4; i++)
#pragma unroll
        for (int j = 0; j < 4; j++)
#pragma unroll
            for (int e = 0; e < 4; e++) acc[i][j][e] = 0.f;

    // conversion mapping: thread -> row tid/2, k-half tid&1; 2 float4 each
    const int crow = tid >> 1;
    const int chalf = tid & 1;
    const int cv = node0 + crow;
    const int cvc = cv < NN ? cv : (NN - 1);
    const int crot = 4 * ((crow >> 1) & 3);

    for (int kt = 0; kt < 32; kt++) {
        if (kt) __syncthreads();          // previous compute done before overwrite

        const int seg = kt >> 3;          // 0..3
        const float* Wseg = (seg == 0) ? W0 : (seg == 1) ? W1 : (seg == 2) ? W2 : Wh;
        const float csr = (seg < 3) ? cs[seg][crow] : 0.f;

#pragma unroll
        for (int i = 0; i < 2; i++) {
            int k0 = chalf * 8 + i * 4;               // 0..12, local k in chunk
            int kg = (kt & 7) * 16 + k0;              // 0..127 within segment
            // ---- A = G - c*x (segs 0..2) or x (seg 3) ----
            float4 a4;
            const float4* xp = (const float4*)(x + (size_t)cvc * DIM + kg);
            if (seg < 3) {
                float4 gg = __ldg((const float4*)(g_buf + ((size_t)seg * NN + cvc) * DIM + kg));
                float4 xv = __ldg(xp);
                a4.x = fmaf(-csr, xv.x, gg.x);
                a4.y = fmaf(-csr, xv.y, gg.y);
                a4.z = fmaf(-csr, xv.z, gg.z);
                a4.w = fmaf(-csr, xv.w, gg.w);
            } else {
                a4 = __ldg(xp);
            }
            float4 w4 = __ldg((const float4*)(Wseg + (size_t)crow * DIM + kg));

            int rot = (k0 + crot) & 15;               // 4-aligned, <=12
            uint4 h, l;
            split_tf32(a4.x, h.x, l.x); split_tf32(a4.y, h.y, l.y);
            split_tf32(a4.z, h.z, l.z); split_tf32(a4.w, h.w, l.w);
            *(uint4*)&Ah[crow][rot] = h;
            *(uint4*)&Al[crow][rot] = l;
            split_tf32(w4.x, h.x, l.x); split_tf32(w4.y, h.y, l.y);
            split_tf32(w4.z, h.z, l.z); split_tf32(w4.w, h.w, l.w);
            *(uint4*)&Bh[crow][rot] = h;
            *(uint4*)&Bl[crow][rot] = l;
        }
        __syncthreads();

#pragma unroll
        for (int k8 = 0; k8 < 2; k8++) {
            const int kb = k8 * 8;
            // ---- B fragments for 4 n-tiles ----
            uint32_t fbh0[4], fbh1[4], fbl0[4], fbl1[4];
#pragma unroll
            for (int nt = 0; nt < 4; nt++) {
                int n = wn + nt * 8 + g;
                int rb = 4 * ((n >> 1) & 3);
                int i0 = (kb + c + rb) & 15;
                int i1 = (kb + c + 4 + rb) & 15;
                fbh0[nt] = Bh[n][i0];
                fbh1[nt] = Bh[n][i1];
                fbl0[nt] = Bl[n][i0];
                fbl1[nt] = Bl[n][i1];
            }
            // ---- m-tiles: load A frags, 12 mmas each ----
#pragma unroll
            for (int mt = 0; mt < 4; mt++) {
                int m0r = wm + mt * 16 + g;
                int m1r = m0r + 8;                     // same rot class
                int ra = 4 * ((m0r >> 1) & 3);
                int i0 = (kb + c + ra) & 15;
                int i1 = (kb + c + 4 + ra) & 15;
                uint32_t ah0 = Ah[m0r][i0], ah1 = Ah[m1r][i0];
                uint32_t ah2 = Ah[m0r][i1], ah3 = Ah[m1r][i1];
                uint32_t al0 = Al[m0r][i0], al1 = Al[m1r][i0];
                uint32_t al2 = Al[m0r][i1], al3 = Al[m1r][i1];
#pragma unroll
                for (int nt = 0; nt < 4; nt++) {
                    mma_tf32(acc[mt][nt], ah0, ah1, ah2, ah3, fbh0[nt], fbh1[nt]);
                    mma_tf32(acc[mt][nt], ah0, ah1, ah2, ah3, fbl0[nt], fbl1[nt]);
                    mma_tf32(acc[mt][nt], al0, al1, al2, al3, fbh0[nt], fbh1[nt]);
                }
            }
        }
    }

    // ---- epilogue: count-weighted biases, float2 stores ----
#pragma unroll
    for (int mt = 0; mt < 4; mt++) {
#pragma unroll
        for (int half = 0; half < 2; half++) {
            int row = wm + mt * 16 + g + 8 * half;
            int v = node0 + row;
            if (v < NN) {
                float c0 = cs[0][row];
                float c1 = cs[1][row];
                float c2 = cs[2][row];
#pragma unroll
                for (int nt = 0; nt < 4; nt++) {
                    int o = wn + nt * 8 + 2 * c;
                    float r0 = acc[mt][nt][2 * half]
                             + c0 * bias_s[0][o] + c1 * bias_s[1][o]
                             + c2 * bias_s[2][o] + bias_s[3][o];
                    float r1 = acc[mt][nt][2 * half + 1]
                             + c0 * bias_s[0][o + 1] + c1 * bias_s[1][o + 1]
                             + c2 * bias_s[2][o + 1] + bias_s[3][o + 1];
                    *(float2*)(out + (size_t)v * DIM + o) = make_float2(r0, r1);
                }
            }
        }
    }
}

// ---------------------------------------------------------------------------
// Launch
// ---------------------------------------------------------------------------
extern "C" void kernel_launch(void* const* d_in, const int* in_sizes, int n_in,
                              void* d_out, int out_size) {
    const float* n_feats = (const float*)d_in[0];
    const int*   src     = (const int*)d_in[1];
    const int*   dst     = (const int*)d_in[2];
    const int*   e_feats = (const int*)d_in[3];
    const float* W0 = (const float*)d_in[4];
    const float* b0 = (const float*)d_in[5];
    const float* W1 = (const float*)d_in[6];
    const float* b1 = (const float*)d_in[7];
    const float* W2 = (const float*)d_in[8];
    const float* b2 = (const float*)d_in[9];
    const float* Wh = (const float*)d_in[10];
    const float* bh = (const float*)d_in[11];
    float* out = (float*)d_out;

    // Phase 0: zero scratch
    {
        int total = 3 * NN * DIM / 4;
        int grid = (total + 255) / 256;
        zero_kernel<<<grid, 256>>>();
    }

    // Phase 1: edge scatter — one warp per edge (src-only reads)
    {
        int grid = EE / 8;   // 8 warps (edges) per 256-thread block
        scatter_kernel<<<grid, 256>>>((const float4*)n_feats, src, dst, e_feats);
    }

    // Phase 2: 3xTF32 HMMA GEMM + (−cnt·x) correction + biases
    {
        int grid = (NN + 127) / 128;   // 391
        gemm_kernel<<<grid, 256>>>(n_feats, W0, W1, W2, Wh,
                                   b0, b1, b2, bh, out);
    }
}

// round 16
// speedup vs baseline: 1.7718x; 1.2718x over previous
#include <cuda_runtime.h>
#include <cuda_bf16.h>
#include <cstdint>

#define NN 50000
#define EE 800000
#define DIM 128

// Scratch (static device globals — no allocation at launch time).
__device__ float g_buf[3u * NN * DIM];        // per-type src-sum accumulators, 76.8 MB
__device__ float cnt_buf[3u * NN];            // per-type in-degree counts (float, exact)

// ---------------------------------------------------------------------------
// Phase 0: zero accumulators
// ---------------------------------------------------------------------------
__global__ void zero_kernel() {
    const float4 z = make_float4(0.f, 0.f, 0.f, 0.f);
    size_t i = (size_t)blockIdx.x * blockDim.x + threadIdx.x;
    const size_t ng = (size_t)3 * NN * DIM / 4;   // 4.8M float4
    if (i < ng) reinterpret_cast<float4*>(g_buf)[i] = z;
    if (i < (size_t)(3 * NN) / 4) reinterpret_cast<float4*>(cnt_buf)[i] = z;
}

// ---------------------------------------------------------------------------
// Phase 1: edge scatter. One warp per edge.
//   G_t[dst] += x[src];  cnt_t[dst] += 1     (−cnt·x[dst] fused into GEMM)
// ---------------------------------------------------------------------------
__global__ __launch_bounds__(256) void scatter_kernel(
    const float4* __restrict__ x4,
    const int* __restrict__ src, const int* __restrict__ dst,
    const int* __restrict__ et) {
    int warp = (int)(((size_t)blockIdx.x * blockDim.x + threadIdx.x) >> 5);
    int lane = threadIdx.x & 31;
    if (warp >= EE) return;
    int s = __ldg(src + warp);
    int d = __ldg(dst + warp);
    int t = __ldg(et + warp);

    float4 a = x4[(size_t)s * 32 + lane];

    float* p = g_buf + ((size_t)t * NN + d) * DIM + lane * 4;
    asm volatile("red.global.add.v4.f32 [%0], {%1, %2, %3, %4};"
                 :: "l"(p), "f"(a.x), "f"(a.y), "f"(a.z), "f"(a.w) : "memory");

    if (lane == 0) atomicAdd(cnt_buf + (size_t)t * NN + d, 1.0f);
}

// ---------------------------------------------------------------------------
// 3xBF16 helpers (sm_80+ baseline — legal on plain sm_100 target).
// a = hi + lo + O(2^-18 a); D += Ah*Bh + Ah*Bl + Al*Bh leaves ~2^-18 error.
// ---------------------------------------------------------------------------
__device__ __forceinline__ void split_bf16x2(float f0, float f1,
                                             uint32_t& hi, uint32_t& lo) {
    __nv_bfloat16 h0 = __float2bfloat16(f0);
    __nv_bfloat16 h1 = __float2bfloat16(f1);
    float r0 = f0 - __bfloat162float(h0);
    float r1 = f1 - __bfloat162float(h1);
    __nv_bfloat16 l0 = __float2bfloat16(r0);
    __nv_bfloat16 l1 = __float2bfloat16(r1);
    hi = ((uint32_t)__bfloat16_as_ushort(h1) << 16) | __bfloat16_as_ushort(h0);
    lo = ((uint32_t)__bfloat16_as_ushort(l1) << 16) | __bfloat16_as_ushort(l0);
}

__device__ __forceinline__ void mma_bf16(float* acc,
    uint32_t a0, uint32_t a1, uint32_t a2, uint32_t a3,
    uint32_t b0, uint32_t b1) {
    asm volatile(
        "mma.sync.aligned.m16n8k16.row.col.f32.bf16.bf16.f32 "
        "{%0,%1,%2,%3}, {%4,%5,%6,%7}, {%8,%9}, {%0,%1,%2,%3};"
        : "+f"(acc[0]), "+f"(acc[1]), "+f"(acc[2]), "+f"(acc[3])
        : "r"(a0), "r"(a1), "r"(a2), "r"(a3), "r"(b0), "r"(b1));
}

// ---------------------------------------------------------------------------
// Phase 2: out[N,128] = A[N,512] @ Wcat^T + bias(counts)  via 3xBF16 HMMA.
//   A[v,k] = G_t[v][kk] - cnt_t[v]*x[v][kk]  (t=k/128<3),  x[v][k-384] else.
// CTA: 128 nodes x 128 outs, 256 threads = 8 warps (2m x 4n), warp 64x32.
// K=512 in 32 chunks of BK=16; DOUBLE-BUFFERED smem (bf16x2-packed planes),
// one barrier per chunk; G/x LDGs staged in regs so DRAM latency hides
// under the MMA block. Rotation rot(r)=4*((r>>2)&1) on k2-blocks makes all
// fragment LDS 32-bank conflict-free.
// ---------------------------------------------------------------------------
__global__ __launch_bounds__(256, 2) void gemm_kernel(
    const float* __restrict__ x,
    const float* __restrict__ W0, const float* __restrict__ W1,
    const float* __restrict__ W2, const float* __restrict__ Wh,
    const float* __restrict__ b0, const float* __restrict__ b1,
    const float* __restrict__ b2, const float* __restrict__ bh,
    float* __restrict__ out) {
    __shared__ uint32_t Ah[2][128][8], Al[2][128][8];
    __shared__ uint32_t Bh[2][128][8], Bl[2][128][8];
    __shared__ float cs[3][128];
    __shared__ float bias_s[4][128];

    const int tid = threadIdx.x;
    const int lane = tid & 31;
    const int warp = tid >> 5;
    const int node0 = blockIdx.x * 128;

    if (tid < 128) {
        int v = node0 + tid;
        int vc = v < NN ? v : (NN - 1);
        bool ok = v < NN;
        cs[0][tid] = ok ? cnt_buf[0 * NN + vc] : 0.f;
        cs[1][tid] = ok ? cnt_buf[1 * NN + vc] : 0.f;
        cs[2][tid] = ok ? cnt_buf[2 * NN + vc] : 0.f;
    }
#pragma unroll
    for (int r = 0; r < 2; r++) {
        int f = tid + r * 256;
        int t = f >> 7, o = f & 127;
        const float* bp = (t == 0) ? b0 : (t == 1) ? b1 : (t == 2) ? b2 : bh;
        bias_s[t][o] = bp[o];
    }
    __syncthreads();

    const int wm = (warp >> 2) * 64;     // 0 / 64
    const int wn = (warp & 3) * 32;      // 0/32/64/96
    const int g = lane >> 2;             // 0..7
    const int c = lane & 3;              // 0..3

    float acc[4][4][4];                   // [mt][nt][frag]
#pragma unroll
    for (int i = 0; i < 4; i++)
#pragma unroll
        for (int j = 0; j < 4; j++)
#pragma unroll
            for (int e = 0; e < 4; e++) acc[i][j][e] = 0.f;

    // conversion mapping: thread -> row tid/2 (0..127), k-half tid&1 (8 k)
    const int crow = tid >> 1;
    const int chalf = tid & 1;
    const int cv = node0 + crow;
    const int cvc = cv < NN ? cv : (NN - 1);
    const int crot = 4 * ((crow >> 2) & 1);
    const int cblk = (chalf * 4) ^ crot;           // u32 block base in row

    // staged LDG registers (A-side only; W is L1/L2-hot)
    float4 sg0, sg1, sx0, sx1;

    auto ldg_stage = [&](int kt) {
        const int seg = kt >> 3;
        const int kg = (kt & 7) * 16 + chalf * 8;
        sx0 = __ldg((const float4*)(x + (size_t)cvc * DIM + kg));
        sx1 = __ldg((const float4*)(x + (size_t)cvc * DIM + kg + 4));
        if (seg < 3) {
            const float* gp = g_buf + ((size_t)seg * NN + cvc) * DIM + kg;
            sg0 = __ldg((const float4*)gp);
            sg1 = __ldg((const float4*)(gp + 4));
        }
    };
    auto cvt_sts = [&](int kt, int buf) {
        const int seg = kt >> 3;
        const int kg = (kt & 7) * 16 + chalf * 8;
        float a[8];
        if (seg < 3) {
            float csr = cs[seg][crow];
            a[0] = fmaf(-csr, sx0.x, sg0.x); a[1] = fmaf(-csr, sx0.y, sg0.y);
            a[2] = fmaf(-csr, sx0.z, sg0.z); a[3] = fmaf(-csr, sx0.w, sg0.w);
            a[4] = fmaf(-csr, sx1.x, sg1.x); a[5] = fmaf(-csr, sx1.y, sg1.y);
            a[6] = fmaf(-csr, sx1.z, sg1.z); a[7] = fmaf(-csr, sx1.w, sg1.w);
        } else {
            a[0] = sx0.x; a[1] = sx0.y; a[2] = sx0.z; a[3] = sx0.w;
            a[4] = sx1.x; a[5] = sx1.y; a[6] = sx1.z; a[7] = sx1.w;
        }
        const float* Wseg = (seg == 0) ? W0 : (seg == 1) ? W1 : (seg == 2) ? W2 : Wh;
        float4 w0 = __ldg((const float4*)(Wseg + (size_t)crow * DIM + kg));
        float4 w1 = __ldg((const float4*)(Wseg + (size_t)crow * DIM + kg + 4));
        float w[8] = {w0.x, w0.y, w0.z, w0.w, w1.x, w1.y, w1.z, w1.w};

        uint4 h, l;
        split_bf16x2(a[0], a[1], h.x, l.x); split_bf16x2(a[2], a[3], h.y, l.y);
        split_bf16x2(a[4], a[5], h.z, l.z); split_bf16x2(a[6], a[7], h.w, l.w);
        *(uint4*)&Ah[buf][crow][cblk] = h;
        *(uint4*)&Al[buf][crow][cblk] = l;
        split_bf16x2(w[0], w[1], h.x, l.x); split_bf16x2(w[2], w[3], h.y, l.y);
        split_bf16x2(w[4], w[5], h.z, l.z); split_bf16x2(w[6], w[7], h.w, l.w);
        *(uint4*)&Bh[buf][crow][cblk] = h;
        *(uint4*)&Bl[buf][crow][cblk] = l;
    };

    ldg_stage(0);
    cvt_sts(0, 0);
    __syncthreads();

    for (int kt = 0; kt < 32; kt++) {
        const int buf = kt & 1;
        if (kt < 31) ldg_stage(kt + 1);   // DRAM latency hides under MMAs

        // ---- B fragments for 4 n-tiles ----
        uint32_t fbh0[4], fbh1[4], fbl0[4], fbl1[4];
#pragma unroll
        for (int nt = 0; nt < 4; nt++) {
            int n = wn + nt * 8 + g;
            int rot = 4 * ((n >> 2) & 1);
            int i0 = (c + rot) & 7;
            int i1 = i0 ^ 4;
            fbh0[nt] = Bh[buf][n][i0];
            fbh1[nt] = Bh[buf][n][i1];
            fbl0[nt] = Bl[buf][n][i0];
            fbl1[nt] = Bl[buf][n][i1];
        }
        // ---- m-tiles ----
#pragma unroll
        for (int mt = 0; mt < 4; mt++) {
            int m0r = wm + mt * 16 + g;
            int m1r = m0r + 8;                     // same rotation class
            int rot = 4 * ((m0r >> 2) & 1);
            int i0 = (c + rot) & 7;
            int i1 = i0 ^ 4;
            uint32_t ah0 = Ah[buf][m0r][i0], ah1 = Ah[buf][m1r][i0];
            uint32_t ah2 = Ah[buf][m0r][i1], ah3 = Ah[buf][m1r][i1];
            uint32_t al0 = Al[buf][m0r][i0], al1 = Al[buf][m1r][i0];
            uint32_t al2 = Al[buf][m0r][i1], al3 = Al[buf][m1r][i1];
#pragma unroll
            for (int nt = 0; nt < 4; nt++) {
                mma_bf16(acc[mt][nt], ah0, ah1, ah2, ah3, fbh0[nt], fbh1[nt]);
                mma_bf16(acc[mt][nt], ah0, ah1, ah2, ah3, fbl0[nt], fbl1[nt]);
                mma_bf16(acc[mt][nt], al0, al1, al2, al3, fbh0[nt], fbh1[nt]);
            }
        }

        if (kt < 31) cvt_sts(kt + 1, buf ^ 1);
        __syncthreads();
    }

    // ---- epilogue: count-weighted biases, float2 stores ----
#pragma unroll
    for (int mt = 0; mt < 4; mt++) {
#pragma unroll
        for (int half = 0; half < 2; half++) {
            int row = wm + mt * 16 + g + 8 * half;
            int v = node0 + row;
            if (v < NN) {
                float c0 = cs[0][row];
                float c1 = cs[1][row];
                float c2 = cs[2][row];
#pragma unroll
                for (int nt = 0; nt < 4; nt++) {
                    int o = wn + nt * 8 + 2 * c;
                    float r0 = acc[mt][nt][2 * half]
                             + c0 * bias_s[0][o] + c1 * bias_s[1][o]
                             + c2 * bias_s[2][o] + bias_s[3][o];
                    float r1 = acc[mt][nt][2 * half + 1]
                             + c0 * bias_s[0][o + 1] + c1 * bias_s[1][o + 1]
                             + c2 * bias_s[2][o + 1] + bias_s[3][o + 1];
                    *(float2*)(out + (size_t)v * DIM + o) = make_float2(r0, r1);
                }
            }
        }
    }
}

// ---------------------------------------------------------------------------
// Launch
// ---------------------------------------------------------------------------
extern "C" void kernel_launch(void* const* d_in, const int* in_sizes, int n_in,
                              void* d_out, int out_size) {
    const float* n_feats = (const float*)d_in[0];
    const int*   src     = (const int*)d_in[1];
    const int*   dst     = (const int*)d_in[2];
    const int*   e_feats = (const int*)d_in[3];
    const float* W0 = (const float*)d_in[4];
    const float* b0 = (const float*)d_in[5];
    const float* W1 = (const float*)d_in[6];
    const float* b1 = (const float*)d_in[7];
    const float* W2 = (const float*)d_in[8];
    const float* b2 = (const float*)d_in[9];
    const float* Wh = (const float*)d_in[10];
    const float* bh = (const float*)d_in[11];
    float* out = (float*)d_out;

    // Phase 0: zero scratch
    {
        int total = 3 * NN * DIM / 4;
        int grid = (total + 255) / 256;
        zero_kernel<<<grid, 256>>>();
    }

    // Phase 1: edge scatter — one warp per edge (src-only reads)
    {
        int grid = EE / 8;   // 8 warps (edges) per 256-thread block
        scatter_kernel<<<grid, 256>>>((const float4*)n_feats, src, dst, e_feats);
    }

    // Phase 2: 3xBF16 HMMA GEMM (double-buffered) + (−cnt·x) + biases
    {
        int grid = (NN + 127) / 128;   // 391
        gemm_kernel<<<grid, 256>>>(n_feats, W0, W1, W2, Wh,
                                   b0, b1, b2, bh, out);
    }
}

// round 17
// speedup vs baseline: 2.1790x; 1.2298x over previous
#include <cuda_runtime.h>
#include <cuda_bf16.h>
#include <cstdint>

#define NN 50000
#define EE 800000
#define DIM 128
#define NCELL (3 * NN)              // 150000 (node,type) cells
#define NB 586                      // ceil(NCELL/256)

// Scratch (static device globals — no allocation at launch time).
__device__ float g_buf[3u * NN * DIM];   // per-type src-sum accumulators, 76.8 MB
__device__ int   deg_buf[NCELL];         // per-cell in-degree (histogram)
__device__ int   offs_buf[NCELL];        // CSR offsets (exclusive scan of deg)
__device__ int   cur_buf[NCELL];         // fill cursors
__device__ int   esrc_buf[EE];           // edge sources bucketed by (type,dst)
__device__ int   blksum_buf[1024];       // block sums for 2-level scan
__device__ int   blkpref_buf[1024];      // block prefixes

// ---------------------------------------------------------------------------
// CSR build: zero degrees -> histogram -> 2-level scan -> fill
// ---------------------------------------------------------------------------
__global__ void zero_deg_kernel() {
    int i = blockIdx.x * blockDim.x + threadIdx.x;
    if (i < NCELL) deg_buf[i] = 0;
}

__global__ void hist_kernel(const int* __restrict__ dst,
                            const int* __restrict__ et) {
    int e = blockIdx.x * blockDim.x + threadIdx.x;
    if (e < EE) atomicAdd(&deg_buf[et[e] * NN + dst[e]], 1);
}

// intra-block exclusive scan + block totals
__global__ void scan1_kernel() {
    __shared__ int s[256];
    int tid = threadIdx.x;
    int i = blockIdx.x * 256 + tid;
    int v = (i < NCELL) ? deg_buf[i] : 0;
    s[tid] = v;
    __syncthreads();
#pragma unroll
    for (int off = 1; off < 256; off <<= 1) {
        int t = (tid >= off) ? s[tid - off] : 0;
        __syncthreads();
        s[tid] += t;
        __syncthreads();
    }
    if (i < NCELL) offs_buf[i] = s[tid] - v;       // exclusive
    if (tid == 255) blksum_buf[blockIdx.x] = s[255];
}

// single-block exclusive scan of the 586 block sums
__global__ void scan2_kernel() {
    __shared__ int s[1024];
    int tid = threadIdx.x;
    int v = (tid < NB) ? blksum_buf[tid] : 0;
    s[tid] = v;
    __syncthreads();
#pragma unroll
    for (int off = 1; off < 1024; off <<= 1) {
        int t = (tid >= off) ? s[tid - off] : 0;
        __syncthreads();
        s[tid] += t;
        __syncthreads();
    }
    if (tid < NB) blkpref_buf[tid] = s[tid] - v;   // exclusive
}

__global__ void scan3_kernel() {
    int i = blockIdx.x * 256 + threadIdx.x;
    if (i < NCELL) {
        int o = offs_buf[i] + blkpref_buf[blockIdx.x];
        offs_buf[i] = o;
        cur_buf[i] = o;
    }
}

__global__ void fill_kernel(const int* __restrict__ src,
                            const int* __restrict__ dst,
                            const int* __restrict__ et) {
    int e = blockIdx.x * blockDim.x + threadIdx.x;
    if (e < EE) {
        int pos = atomicAdd(&cur_buf[et[e] * NN + dst[e]], 1);
        esrc_buf[pos] = src[e];
    }
}

// ---------------------------------------------------------------------------
// Gather: one warp per (type,dst) cell. Plain stores, no atomics, no zeroing.
//   G[cell] = sum_{e in cell} x[src_e]
// ---------------------------------------------------------------------------
__global__ __launch_bounds__(256) void gather_kernel(const float4* __restrict__ x4) {
    int cell = (int)(((size_t)blockIdx.x * blockDim.x + threadIdx.x) >> 5);
    int lane = threadIdx.x & 31;
    if (cell >= NCELL) return;
    int d = deg_buf[cell];
    int base = offs_buf[cell];
    float4 acc = make_float4(0.f, 0.f, 0.f, 0.f);
    for (int j = 0; j < d; j++) {
        int sid = __ldg(&esrc_buf[base + j]);      // converged broadcast
        float4 a = __ldg(&x4[(size_t)sid * 32 + lane]);
        acc.x += a.x; acc.y += a.y; acc.z += a.z; acc.w += a.w;
    }
    reinterpret_cast<float4*>(g_buf)[(size_t)cell * 32 + lane] = acc;
}

// ---------------------------------------------------------------------------
// 3xBF16 helpers (sm_80+ baseline — legal on plain sm_100 target).
// ---------------------------------------------------------------------------
__device__ __forceinline__ void split_bf16x2(float f0, float f1,
                                             uint32_t& hi, uint32_t& lo) {
    __nv_bfloat16 h0 = __float2bfloat16(f0);
    __nv_bfloat16 h1 = __float2bfloat16(f1);
    float r0 = f0 - __bfloat162float(h0);
    float r1 = f1 - __bfloat162float(h1);
    __nv_bfloat16 l0 = __float2bfloat16(r0);
    __nv_bfloat16 l1 = __float2bfloat16(r1);
    hi = ((uint32_t)__bfloat16_as_ushort(h1) << 16) | __bfloat16_as_ushort(h0);
    lo = ((uint32_t)__bfloat16_as_ushort(l1) << 16) | __bfloat16_as_ushort(l0);
}

__device__ __forceinline__ void mma_bf16(float* acc,
    uint32_t a0, uint32_t a1, uint32_t a2, uint32_t a3,
    uint32_t b0, uint32_t b1) {
    asm volatile(
        "mma.sync.aligned.m16n8k16.row.col.f32.bf16.bf16.f32 "
        "{%0,%1,%2,%3}, {%4,%5,%6,%7}, {%8,%9}, {%0,%1,%2,%3};"
        : "+f"(acc[0]), "+f"(acc[1]), "+f"(acc[2]), "+f"(acc[3])
        : "r"(a0), "r"(a1), "r"(a2), "r"(a3), "r"(b0), "r"(b1));
}

// ---------------------------------------------------------------------------
// Phase 2: out[N,128] = A[N,512] @ Wcat^T + bias(counts)  via 3xBF16 HMMA.
// Identical to R16 except counts come from deg_buf (int) instead of cnt_buf.
// ---------------------------------------------------------------------------
__global__ __launch_bounds__(256, 2) void gemm_kernel(
    const float* __restrict__ x,
    const float* __restrict__ W0, const float* __restrict__ W1,
    const float* __restrict__ W2, const float* __restrict__ Wh,
    const float* __restrict__ b0, const float* __restrict__ b1,
    const float* __restrict__ b2, const float* __restrict__ bh,
    float* __restrict__ out) {
    __shared__ uint32_t Ah[2][128][8], Al[2][128][8];
    __shared__ uint32_t Bh[2][128][8], Bl[2][128][8];
    __shared__ float cs[3][128];
    __shared__ float bias_s[4][128];

    const int tid = threadIdx.x;
    const int lane = tid & 31;
    const int warp = tid >> 5;
    const int node0 = blockIdx.x * 128;

    if (tid < 128) {
        int v = node0 + tid;
        int vc = v < NN ? v : (NN - 1);
        bool ok = v < NN;
        cs[0][tid] = ok ? (float)deg_buf[0 * NN + vc] : 0.f;
        cs[1][tid] = ok ? (float)deg_buf[1 * NN + vc] : 0.f;
        cs[2][tid] = ok ? (float)deg_buf[2 * NN + vc] : 0.f;
    }
#pragma unroll
    for (int r = 0; r < 2; r++) {
        int f = tid + r * 256;
        int t = f >> 7, o = f & 127;
        const float* bp = (t == 0) ? b0 : (t == 1) ? b1 : (t == 2) ? b2 : bh;
        bias_s[t][o] = bp[o];
    }
    __syncthreads();

    const int wm = (warp >> 2) * 64;     // 0 / 64
    const int wn = (warp & 3) * 32;      // 0/32/64/96
    const int g = lane >> 2;             // 0..7
    const int c = lane & 3;              // 0..3

    float acc[4][4][4];                   // [mt][nt][frag]
#pragma unroll
    for (int i = 0; i < 4; i++)
#pragma unroll
        for (int j = 0; j < 4; j++)
#pragma unroll
            for (int e = 0; e < 4; e++) acc[i][j][e] = 0.f;

    // conversion mapping: thread -> row tid/2 (0..127), k-half tid&1 (8 k)
    const int crow = tid >> 1;
    const int chalf = tid & 1;
    const int cv = node0 + crow;
    const int cvc = cv < NN ? cv : (NN - 1);
    const int crot = 4 * ((crow >> 2) & 1);
    const int cblk = (chalf * 4) ^ crot;           // u32 block base in row

    // staged LDG registers (A-side only; W is L1/L2-hot)
    float4 sg0, sg1, sx0, sx1;

    auto ldg_stage = [&](int kt) {
        const int seg = kt >> 3;
        const int kg = (kt & 7) * 16 + chalf * 8;
        sx0 = __ldg((const float4*)(x + (size_t)cvc * DIM + kg));
        sx1 = __ldg((const float4*)(x + (size_t)cvc * DIM + kg + 4));
        if (seg < 3) {
            const float* gp = g_buf + ((size_t)seg * NN + cvc) * DIM + kg;
            sg0 = __ldg((const float4*)gp);
            sg1 = __ldg((const float4*)(gp + 4));
        }
    };
    auto cvt_sts = [&](int kt, int buf) {
        const int seg = kt >> 3;
        const int kg = (kt & 7) * 16 + chalf * 8;
        float a[8];
        if (seg < 3) {
            float csr = cs[seg][crow];
            a[0] = fmaf(-csr, sx0.x, sg0.x); a[1] = fmaf(-csr, sx0.y, sg0.y);
            a[2] = fmaf(-csr, sx0.z, sg0.z); a[3] = fmaf(-csr, sx0.w, sg0.w);
            a[4] = fmaf(-csr, sx1.x, sg1.x); a[5] = fmaf(-csr, sx1.y, sg1.y);
            a[6] = fmaf(-csr, sx1.z, sg1.z); a[7] = fmaf(-csr, sx1.w, sg1.w);
        } else {
            a[0] = sx0.x; a[1] = sx0.y; a[2] = sx0.z; a[3] = sx0.w;
            a[4] = sx1.x; a[5] = sx1.y; a[6] = sx1.z; a[7] = sx1.w;
        }
        const float* Wseg = (seg == 0) ? W0 : (seg == 1) ? W1 : (seg == 2) ? W2 : Wh;
        float4 w0 = __ldg((const float4*)(Wseg + (size_t)crow * DIM + kg));
        float4 w1 = __ldg((const float4*)(Wseg + (size_t)crow * DIM + kg + 4));
        float w[8] = {w0.x, w0.y, w0.z, w0.w, w1.x, w1.y, w1.z, w1.w};

        uint4 h, l;
        split_bf16x2(a[0], a[1], h.x, l.x); split_bf16x2(a[2], a[3], h.y, l.y);
        split_bf16x2(a[4], a[5], h.z, l.z); split_bf16x2(a[6], a[7], h.w, l.w);
        *(uint4*)&Ah[buf][crow][cblk] = h;
        *(uint4*)&Al[buf][crow][cblk] = l;
        split_bf16x2(w[0], w[1], h.x, l.x); split_bf16x2(w[2], w[3], h.y, l.y);
        split_bf16x2(w[4], w[5], h.z, l.z); split_bf16x2(w[6], w[7], h.w, l.w);
        *(uint4*)&Bh[buf][crow][cblk] = h;
        *(uint4*)&Bl[buf][crow][cblk] = l;
    };

    ldg_stage(0);
    cvt_sts(0, 0);
    __syncthreads();

    for (int kt = 0; kt < 32; kt++) {
        const int buf = kt & 1;
        if (kt < 31) ldg_stage(kt + 1);   // DRAM latency hides under MMAs

        uint32_t fbh0[4], fbh1[4], fbl0[4], fbl1[4];
#pragma unroll
        for (int nt = 0; nt < 4; nt++) {
            int n = wn + nt * 8 + g;
            int rot = 4 * ((n >> 2) & 1);
            int i0 = (c + rot) & 7;
            int i1 = i0 ^ 4;
            fbh0[nt] = Bh[buf][n][i0];
            fbh1[nt] = Bh[buf][n][i1];
            fbl0[nt] = Bl[buf][n][i0];
            fbl1[nt] = Bl[buf][n][i1];
        }
#pragma unroll
        for (int mt = 0; mt < 4; mt++) {
            int m0r = wm + mt * 16 + g;
            int m1r = m0r + 8;
            int rot = 4 * ((m0r >> 2) & 1);
            int i0 = (c + rot) & 7;
            int i1 = i0 ^ 4;
            uint32_t ah0 = Ah[buf][m0r][i0], ah1 = Ah[buf][m1r][i0];
            uint32_t ah2 = Ah[buf][m0r][i1], ah3 = Ah[buf][m1r][i1];
            uint32_t al0 = Al[buf][m0r][i0], al1 = Al[buf][m1r][i0];
            uint32_t al2 = Al[buf][m0r][i1], al3 = Al[buf][m1r][i1];
#pragma unroll
            for (int nt = 0; nt < 4; nt++) {
                mma_bf16(acc[mt][nt], ah0, ah1, ah2, ah3, fbh0[nt], fbh1[nt]);
                mma_bf16(acc[mt][nt], ah0, ah1, ah2, ah3, fbl0[nt], fbl1[nt]);
                mma_bf16(acc[mt][nt], al0, al1, al2, al3, fbh0[nt], fbh1[nt]);
            }
        }

        if (kt < 31) cvt_sts(kt + 1, buf ^ 1);
        __syncthreads();
    }

    // ---- epilogue: count-weighted biases, float2 stores ----
#pragma unroll
    for (int mt = 0; mt < 4; mt++) {
#pragma unroll
        for (int half = 0; half < 2; half++) {
            int row = wm + mt * 16 + g + 8 * half;
            int v = node0 + row;
            if (v < NN) {
                float c0 = cs[0][row];
                float c1 = cs[1][row];
                float c2 = cs[2][row];
#pragma unroll
                for (int nt = 0; nt < 4; nt++) {
                    int o = wn + nt * 8 + 2 * c;
                    float r0 = acc[mt][nt][2 * half]
                             + c0 * bias_s[0][o] + c1 * bias_s[1][o]
                             + c2 * bias_s[2][o] + bias_s[3][o];
                    float r1 = acc[mt][nt][2 * half + 1]
                             + c0 * bias_s[0][o + 1] + c1 * bias_s[1][o + 1]
                             + c2 * bias_s[2][o + 1] + bias_s[3][o + 1];
                    *(float2*)(out + (size_t)v * DIM + o) = make_float2(r0, r1);
                }
            }
        }
    }
}

// ---------------------------------------------------------------------------
// Launch
// ---------------------------------------------------------------------------
extern "C" void kernel_launch(void* const* d_in, const int* in_sizes, int n_in,
                              void* d_out, int out_size) {
    const float* n_feats = (const float*)d_in[0];
    const int*   src     = (const int*)d_in[1];
    const int*   dst     = (const int*)d_in[2];
    const int*   e_feats = (const int*)d_in[3];
    const float* W0 = (const float*)d_in[4];
    const float* b0 = (const float*)d_in[5];
    const float* W1 = (const float*)d_in[6];
    const float* b1 = (const float*)d_in[7];
    const float* W2 = (const float*)d_in[8];
    const float* b2 = (const float*)d_in[9];
    const float* Wh = (const float*)d_in[10];
    const float* bh = (const float*)d_in[11];
    float* out = (float*)d_out;

    const int EB = (EE + 255) / 256;     // 3125 edge blocks

    // CSR build
    zero_deg_kernel<<<NB, 256>>>();
    hist_kernel<<<EB, 256>>>(dst, e_feats);
    scan1_kernel<<<NB, 256>>>();
    scan2_kernel<<<1, 1024>>>();
    scan3_kernel<<<NB, 256>>>();
    fill_kernel<<<EB, 256>>>(src, dst, e_feats);

    // Gather: one warp per (type,dst) cell -> G (no atomics, no zeroing)
    {
        int grid = (NCELL * 32 + 255) / 256;   // 18750
        gather_kernel<<<grid, 256>>>((const float4*)n_feats);
    }

    // 3xBF16 HMMA GEMM (double-buffered) + (−cnt·x) + biases
    {
        int grid = (NN + 127) / 128;   // 391
        gemm_kernel<<<grid, 256>>>(n_feats, W0, W1, W2, Wh,
                                   b0, b1, b2, bh, out);
    }
}